// round 4
// baseline (speedup 1.0000x reference)
#include <cuda_runtime.h>
#include <math.h>

#define FULLMASK 0xffffffffu
#define NTOK 64
#define HDIM 4096
#define QKVN 6144
#define PAST 4096
#define TOT  4100
#define OUT_OFF 262144
#define NEWK_ELEMS 67174400

// ------------------------- scratch (allocation-free) ------------------------
__device__ float g_part[8 * 64 * 6144];   // split-K partials (12.6 MB)
__device__ float g_q   [64 * 4096];       // roped Q, token-major
__device__ float g_attn[64 * 4096];       // attention output (pre w_o)
__device__ float g_knew[64 * 8 * 128];    // roped new K rows
__device__ float g_vnew[64 * 8 * 128];    // new V rows

// ------------------------------ split-K GEMM --------------------------------
// C_partial[ks][64][N] = A[64, 4096(chunk ks)] @ W[4096, N]
// CTA tile 64x128, 256 thr, 8m x 4n per thread, Kc=16, double-buffered smem.
__global__ __launch_bounds__(256) void gemm_splitk(
    const float* __restrict__ Ain, const float* __restrict__ W,
    int N, int useAttn)
{
    const float* A = useAttn ? g_attn : Ain;
    __shared__ float As[2][16][64];
    __shared__ float Bs[2][16][128];

    const int tid = threadIdx.x;
    const int n0  = blockIdx.x * 128;
    const int kbase = blockIdx.y * 512;          // Kchunk = 512, KS = 8

    const int lm = tid >> 2,  lk = (tid & 3) << 2;
    const int bk = tid >> 4,  bn = (tid & 15) << 3;

    const float* Ap = A + (size_t)lm * 4096 + kbase + lk;
    const float* Wp = W + (size_t)(kbase + bk) * N + n0 + bn;

    float4 ar  = *(const float4*)Ap;
    float4 br0 = *(const float4*)Wp;
    float4 br1 = *(const float4*)(Wp + 4);

    const int tm = (tid >> 5) << 3;
    const int tn = (tid & 31) << 2;

    float acc[8][4] = {};

    for (int st = 0; st < 32; st++) {            // 32 stages * 16 = 512
        const int cur = st & 1;
        As[cur][lk + 0][lm] = ar.x;
        As[cur][lk + 1][lm] = ar.y;
        As[cur][lk + 2][lm] = ar.z;
        As[cur][lk + 3][lm] = ar.w;
        *(float4*)&Bs[cur][bk][bn]     = br0;
        *(float4*)&Bs[cur][bk][bn + 4] = br1;
        __syncthreads();
        if (st + 1 < 32) {
            ar  = *(const float4*)(Ap + (st + 1) * 16);
            br0 = *(const float4*)(Wp + (size_t)(st + 1) * 16 * N);
            br1 = *(const float4*)(Wp + (size_t)(st + 1) * 16 * N + 4);
        }
        #pragma unroll
        for (int k = 0; k < 16; k++) {
            float4 b4 = *(const float4*)&Bs[cur][k][tn];
            #pragma unroll
            for (int i = 0; i < 8; i++) {
                float a = As[cur][k][tm + i];
                acc[i][0] += a * b4.x;
                acc[i][1] += a * b4.y;
                acc[i][2] += a * b4.z;
                acc[i][3] += a * b4.w;
            }
        }
    }

    float* out = g_part + (size_t)blockIdx.y * 64 * N;
    #pragma unroll
    for (int i = 0; i < 8; i++) {
        float4 v = make_float4(acc[i][0], acc[i][1], acc[i][2], acc[i][3]);
        *(float4*)&out[(size_t)(tm + i) * N + n0 + tn] = v;
    }
}

// ---------------- reduce split-K partials + RoPE + scatter ------------------
__global__ __launch_bounds__(256) void reduce_rope(
    const int* __restrict__ positions,
    float* __restrict__ out_newk, float* __restrict__ out_newv)
{
    int idx = blockIdx.x * 256 + threadIdx.x;    // 229376 total
    if (idx < 131072) {                          // Q rope pairs: 64*32*64
        int tok = idx >> 11;
        int rem = idx & 2047;
        int h = rem >> 6, d = rem & 63;
        int col = h * 128 + d;
        float v1 = 0.f, v2 = 0.f;
        #pragma unroll
        for (int ks = 0; ks < 8; ks++) {
            const float* p = g_part + (size_t)(ks * 64 + tok) * 6144;
            v1 += p[col];
            v2 += p[col + 64];
        }
        float pos = (float)positions[tok];
        float inv = powf(500000.0f, -(float)d * (1.0f / 64.0f));
        float sn, cs;
        sincosf(pos * inv, &sn, &cs);
        g_q[tok * 4096 + col]      = v1 * cs - v2 * sn;
        g_q[tok * 4096 + col + 64] = v2 * cs + v1 * sn;
    } else if (idx < 163840) {                   // K rope pairs: 64*8*64
        int j = idx - 131072;
        int tok = j >> 9;
        int rem = j & 511;
        int kv = rem >> 6, d = rem & 63;
        int col = 4096 + kv * 128 + d;
        float v1 = 0.f, v2 = 0.f;
        #pragma unroll
        for (int ks = 0; ks < 8; ks++) {
            const float* p = g_part + (size_t)(ks * 64 + tok) * 6144;
            v1 += p[col];
            v2 += p[col + 64];
        }
        float pos = (float)positions[tok];
        float inv = powf(500000.0f, -(float)d * (1.0f / 64.0f));
        float sn, cs;
        sincosf(pos * inv, &sn, &cs);
        float o1 = v1 * cs - v2 * sn;
        float o2 = v2 * cs + v1 * sn;
        g_knew[(tok * 8 + kv) * 128 + d]      = o1;
        g_knew[(tok * 8 + kv) * 128 + d + 64] = o2;
        int b = tok >> 2, s = tok & 3;
        size_t oo = ((size_t)(b * TOT + PAST + s) * 8 + kv) * 128 + d;
        out_newk[oo]      = o1;
        out_newk[oo + 64] = o2;
    } else {                                     // V passthrough: 64*8*128
        int j = idx - 163840;
        int tok = j >> 10;
        int rem = j & 1023;
        int kv = rem >> 7, d = rem & 127;
        int col = 5120 + kv * 128 + d;
        float v = 0.f;
        #pragma unroll
        for (int ks = 0; ks < 8; ks++)
            v += g_part[(size_t)(ks * 64 + tok) * 6144 + col];
        g_vnew[(tok * 8 + kv) * 128 + d] = v;
        int b = tok >> 2, s = tok & 3;
        out_newv[((size_t)(b * TOT + PAST + s) * 8 + kv) * 128 + d] = v;
    }
}

// ----------------- fused attention + KV-cache copy --------------------------
// grid = 128 CTAs, one per (b, kv_head). 256 threads.
__device__ __forceinline__ void load_tile(
    int ti, int tid, int b, int g,
    const float* __restrict__ pk, const float* __restrict__ pv,
    float4 kr[4], float4 vr[4])
{
    #pragma unroll
    for (int j = 0; j < 4; j++) {
        int idx = tid + j * 256;
        int t = idx >> 5, d4 = idx & 31;
        if (ti < 128) {
            size_t base = ((size_t)(b * PAST + ti * 32 + t) * 8 + g) * 128 + d4 * 4;
            kr[j] = *(const float4*)(pk + base);
            vr[j] = *(const float4*)(pv + base);
        } else if (t < 4) {
            size_t base = ((size_t)(b * 4 + t) * 8 + g) * 128 + d4 * 4;
            kr[j] = *(const float4*)(g_knew + base);
            vr[j] = *(const float4*)(g_vnew + base);
        } else {
            kr[j] = make_float4(0.f, 0.f, 0.f, 0.f);
            vr[j] = make_float4(0.f, 0.f, 0.f, 0.f);
        }
    }
}

__global__ __launch_bounds__(256) void attn_kernel(
    const float* __restrict__ past_k, const float* __restrict__ past_v,
    float* __restrict__ out_newk, float* __restrict__ out_newv)
{
    __shared__ float4 qs[16][32];
    __shared__ float4 ksm[32][32];
    __shared__ float4 vsm[32][32];

    const int tid = threadIdx.x;
    const int lane = tid & 31, w = tid >> 5;
    const int b = blockIdx.x >> 3, g = blockIdx.x & 7;

    // load roped Q for this (b,g): 16 rows (s,r) x 128
    for (int i = tid; i < 512; i += 256) {
        int q = i >> 5, d4 = i & 31;
        int s = q >> 2, r = q & 3;
        qs[q][d4] = *(const float4*)&g_q[(size_t)(b * 4 + s) * 4096 +
                                         (g * 4 + r) * 128 + d4 * 4];
    }

    const int q0 = 2 * w, q1 = 2 * w + 1;
    float m0 = -1e30f, m1 = -1e30f, l0 = 0.f, l1 = 0.f;
    float4 o0 = make_float4(0.f, 0.f, 0.f, 0.f);
    float4 o1 = make_float4(0.f, 0.f, 0.f, 0.f);
    const float scale = 0.08838834764831845f;   // 1/sqrt(128)

    float4 kr[4], vr[4];
    load_tile(0, tid, b, g, past_k, past_v, kr, vr);

    for (int ti = 0; ti <= 128; ti++) {
        if (ti) __syncthreads();                // smem reuse barrier
        // store tile to smem (XOR swizzle) + fused cache copy-out
        #pragma unroll
        for (int j = 0; j < 4; j++) {
            int idx = tid + j * 256;
            int t = idx >> 5, d4 = idx & 31;
            ksm[t][d4 ^ t] = kr[j];
            vsm[t][d4 ^ t] = vr[j];
            if (ti < 128) {
                size_t ob = ((size_t)(b * TOT + ti * 32 + t) * 8 + g) * 128 + d4 * 4;
                *(float4*)&out_newk[ob] = kr[j];
                *(float4*)&out_newv[ob] = vr[j];
            }
        }
        __syncthreads();
        if (ti < 128) load_tile(ti + 1, tid, b, g, past_k, past_v, kr, vr);

        // scores: warp w -> q rows {q0,q1}, lane -> t
        float s0 = 0.f, s1 = 0.f;
        #pragma unroll
        for (int d4 = 0; d4 < 32; d4++) {
            float4 kk = ksm[lane][d4 ^ lane];
            float4 qa = qs[q0][d4];
            float4 qb = qs[q1][d4];
            s0 += qa.x * kk.x + qa.y * kk.y + qa.z * kk.z + qa.w * kk.w;
            s1 += qb.x * kk.x + qb.y * kk.y + qb.z * kk.z + qb.w * kk.w;
        }
        s0 *= scale;
        s1 *= scale;
        if (ti == 128 && lane >= 4) { s0 = -1e30f; s1 = -1e30f; }

        // online softmax (warp-local)
        float mt0 = s0, mt1 = s1;
        #pragma unroll
        for (int off = 16; off > 0; off >>= 1) {
            mt0 = fmaxf(mt0, __shfl_xor_sync(FULLMASK, mt0, off));
            mt1 = fmaxf(mt1, __shfl_xor_sync(FULLMASK, mt1, off));
        }
        float mn0 = fmaxf(m0, mt0), mn1 = fmaxf(m1, mt1);
        float a0 = expf(m0 - mn0), a1 = expf(m1 - mn1);
        float p0 = expf(s0 - mn0), p1 = expf(s1 - mn1);
        float sp0 = p0, sp1 = p1;
        #pragma unroll
        for (int off = 16; off > 0; off >>= 1) {
            sp0 += __shfl_xor_sync(FULLMASK, sp0, off);
            sp1 += __shfl_xor_sync(FULLMASK, sp1, off);
        }
        l0 = l0 * a0 + sp0;
        l1 = l1 * a1 + sp1;
        m0 = mn0; m1 = mn1;
        o0.x *= a0; o0.y *= a0; o0.z *= a0; o0.w *= a0;
        o1.x *= a1; o1.y *= a1; o1.z *= a1; o1.w *= a1;

        // PV: lane -> d4, broadcast P via shuffle
        #pragma unroll
        for (int t = 0; t < 32; t++) {
            float pp0 = __shfl_sync(FULLMASK, p0, t);
            float pp1 = __shfl_sync(FULLMASK, p1, t);
            float4 vv = vsm[t][lane ^ t];
            o0.x += pp0 * vv.x; o0.y += pp0 * vv.y;
            o0.z += pp0 * vv.z; o0.w += pp0 * vv.w;
            o1.x += pp1 * vv.x; o1.y += pp1 * vv.y;
            o1.z += pp1 * vv.z; o1.w += pp1 * vv.w;
        }
    }

    // epilogue: normalize, write g_attn rows (token, head-col)
    float i0 = 1.f / l0, i1 = 1.f / l1;
    o0.x *= i0; o0.y *= i0; o0.z *= i0; o0.w *= i0;
    o1.x *= i1; o1.y *= i1; o1.z *= i1; o1.w *= i1;
    {
        int s = q0 >> 2, r = q0 & 3;
        *(float4*)&g_attn[(size_t)(b * 4 + s) * 4096 + (g * 4 + r) * 128 + lane * 4] = o0;
        s = q1 >> 2; r = q1 & 3;
        *(float4*)&g_attn[(size_t)(b * 4 + s) * 4096 + (g * 4 + r) * 128 + lane * 4] = o1;
    }
}

// --------------------- final split-K reduce for output ----------------------
__global__ __launch_bounds__(256) void reduce_out(float* __restrict__ out)
{
    int idx = blockIdx.x * 256 + threadIdx.x;   // 262144
    int m = idx >> 12, n = idx & 4095;
    float v = 0.f;
    #pragma unroll
    for (int ks = 0; ks < 8; ks++)
        v += g_part[(size_t)(ks * 64 + m) * 4096 + n];
    out[idx] = v;
}

// -----------------------------------------------------------------------------
extern "C" void kernel_launch(void* const* d_in, const int* in_sizes, int n_in,
                              void* d_out, int out_size)
{
    const int*   positions = (const int*)  d_in[0];
    const float* hidden    = (const float*)d_in[1];
    const float* past_k    = (const float*)d_in[2];
    const float* past_v    = (const float*)d_in[3];
    const float* w_qkv     = (const float*)d_in[4];
    const float* w_o       = (const float*)d_in[5];

    float* out      = (float*)d_out;
    float* out_newk = out + OUT_OFF;
    float* out_newv = out_newk + NEWK_ELEMS;

    gemm_splitk<<<dim3(48, 8), 256>>>(hidden, w_qkv, 6144, 0);
    reduce_rope<<<896, 256>>>(positions, out_newk, out_newv);
    attn_kernel<<<128, 256>>>(past_k, past_v, out_newk, out_newv);
    gemm_splitk<<<dim3(32, 8), 256>>>(nullptr, w_o, 4096, 1);
    reduce_out<<<1024, 256>>>(out);
}

// round 5
// speedup vs baseline: 1.0449x; 1.0449x over previous
#include <cuda_runtime.h>
#include <math.h>

#define FULLMASK 0xffffffffu
#define NTOK 64
#define PAST 4096
#define TOT  4100
#define OUT_OFF 262144
#define NEWK_ELEMS 67174400
#define KS 16

// ------------------------- scratch (allocation-free) ------------------------
__device__ float g_part[KS * 64 * 6144];    // split-K partials (25.2 MB)
__device__ float g_q   [64 * 4096];         // roped Q, token-major
__device__ float g_attn[64 * 4096];         // attention output (pre w_o)
__device__ float g_knew[64 * 8 * 128];      // roped new K rows
__device__ float g_vnew[64 * 8 * 128];      // new V rows
__device__ float g_po  [512 * 16 * 128];    // split-KV partial O (unnormalized)
__device__ float g_pm  [512 * 16];          // split-KV partial max
__device__ float g_pl  [512 * 16];          // split-KV partial sum

// ------------------------------ split-K GEMM --------------------------------
// C_partial[ks][64][N] = A[64, 4096(chunk ks)] @ W[4096, N]
// CTA tile 64x128, 256 thr, 8m x 4n per thread, Kc=16, double-buffered smem.
__global__ __launch_bounds__(256) void gemm_splitk(
    const float* __restrict__ Ain, const float* __restrict__ W,
    int N, int useAttn)
{
    const float* A = useAttn ? g_attn : Ain;
    __shared__ float As[2][16][64];
    __shared__ float Bs[2][16][128];

    const int tid = threadIdx.x;
    const int n0  = blockIdx.x * 128;
    const int kbase = blockIdx.y * 256;          // Kchunk = 256, KS = 16

    const int lm = tid >> 2,  lk = (tid & 3) << 2;
    const int bk = tid >> 4,  bn = (tid & 15) << 3;

    const float* Ap = A + (size_t)lm * 4096 + kbase + lk;
    const float* Wp = W + (size_t)(kbase + bk) * N + n0 + bn;

    float4 ar  = *(const float4*)Ap;
    float4 br0 = *(const float4*)Wp;
    float4 br1 = *(const float4*)(Wp + 4);

    const int tm = (tid >> 5) << 3;
    const int tn = (tid & 31) << 2;

    float acc[8][4] = {};

    for (int st = 0; st < 16; st++) {            // 16 stages * 16 = 256
        const int cur = st & 1;
        As[cur][lk + 0][lm] = ar.x;
        As[cur][lk + 1][lm] = ar.y;
        As[cur][lk + 2][lm] = ar.z;
        As[cur][lk + 3][lm] = ar.w;
        *(float4*)&Bs[cur][bk][bn]     = br0;
        *(float4*)&Bs[cur][bk][bn + 4] = br1;
        __syncthreads();
        if (st + 1 < 16) {
            ar  = *(const float4*)(Ap + (st + 1) * 16);
            br0 = *(const float4*)(Wp + (size_t)(st + 1) * 16 * N);
            br1 = *(const float4*)(Wp + (size_t)(st + 1) * 16 * N + 4);
        }
        #pragma unroll
        for (int k = 0; k < 16; k++) {
            float4 b4  = *(const float4*)&Bs[cur][k][tn];
            float4 alo = *(const float4*)&As[cur][k][tm];
            float4 ahi = *(const float4*)&As[cur][k][tm + 4];
            float a[8] = {alo.x, alo.y, alo.z, alo.w, ahi.x, ahi.y, ahi.z, ahi.w};
            #pragma unroll
            for (int i = 0; i < 8; i++) {
                acc[i][0] += a[i] * b4.x;
                acc[i][1] += a[i] * b4.y;
                acc[i][2] += a[i] * b4.z;
                acc[i][3] += a[i] * b4.w;
            }
        }
    }

    float* out = g_part + (size_t)blockIdx.y * 64 * N;
    #pragma unroll
    for (int i = 0; i < 8; i++) {
        float4 v = make_float4(acc[i][0], acc[i][1], acc[i][2], acc[i][3]);
        *(float4*)&out[(size_t)(tm + i) * N + n0 + tn] = v;
    }
}

// ---------------- reduce split-K partials + RoPE + scatter ------------------
__global__ __launch_bounds__(256) void reduce_rope(
    const int* __restrict__ positions,
    float* __restrict__ out_newk, float* __restrict__ out_newv)
{
    int idx = blockIdx.x * 256 + threadIdx.x;    // 229376 total
    if (idx < 131072) {                          // Q rope pairs: 64*32*64
        int tok = idx >> 11;
        int rem = idx & 2047;
        int h = rem >> 6, d = rem & 63;
        int col = h * 128 + d;
        float v1 = 0.f, v2 = 0.f;
        #pragma unroll
        for (int ks = 0; ks < KS; ks++) {
            const float* p = g_part + (size_t)(ks * 64 + tok) * 6144;
            v1 += p[col];
            v2 += p[col + 64];
        }
        float pos = (float)positions[tok];
        float inv = powf(500000.0f, -(float)d * (1.0f / 64.0f));
        float sn, cs;
        sincosf(pos * inv, &sn, &cs);
        g_q[tok * 4096 + col]      = v1 * cs - v2 * sn;
        g_q[tok * 4096 + col + 64] = v2 * cs + v1 * sn;
    } else if (idx < 163840) {                   // K rope pairs: 64*8*64
        int j = idx - 131072;
        int tok = j >> 9;
        int rem = j & 511;
        int kv = rem >> 6, d = rem & 63;
        int col = 4096 + kv * 128 + d;
        float v1 = 0.f, v2 = 0.f;
        #pragma unroll
        for (int ks = 0; ks < KS; ks++) {
            const float* p = g_part + (size_t)(ks * 64 + tok) * 6144;
            v1 += p[col];
            v2 += p[col + 64];
        }
        float pos = (float)positions[tok];
        float inv = powf(500000.0f, -(float)d * (1.0f / 64.0f));
        float sn, cs;
        sincosf(pos * inv, &sn, &cs);
        float o1 = v1 * cs - v2 * sn;
        float o2 = v2 * cs + v1 * sn;
        g_knew[(tok * 8 + kv) * 128 + d]      = o1;
        g_knew[(tok * 8 + kv) * 128 + d + 64] = o2;
        int b = tok >> 2, s = tok & 3;
        size_t oo = ((size_t)(b * TOT + PAST + s) * 8 + kv) * 128 + d;
        out_newk[oo]      = o1;
        out_newk[oo + 64] = o2;
    } else {                                     // V passthrough: 64*8*128
        int j = idx - 163840;
        int tok = j >> 10;
        int rem = j & 1023;
        int kv = rem >> 7, d = rem & 127;
        int col = 5120 + kv * 128 + d;
        float v = 0.f;
        #pragma unroll
        for (int ks = 0; ks < KS; ks++)
            v += g_part[(size_t)(ks * 64 + tok) * 6144 + col];
        g_vnew[(tok * 8 + kv) * 128 + d] = v;
        int b = tok >> 2, s = tok & 3;
        out_newv[((size_t)(b * TOT + PAST + s) * 8 + kv) * 128 + d] = v;
    }
}

// ----------------- fused attention + KV-cache copy (split-KV x4) ------------
// grid = 512 CTAs: blockIdx.x = ((b*8+g)*4 + sp). Each split streams 1024
// past tokens (32 tiles of 32); split 3 additionally handles the 4 new rows.
__device__ __forceinline__ void load_tile(
    int gt, int tid, int b, int g,
    const float* __restrict__ pk, const float* __restrict__ pv,
    float4 kr[4], float4 vr[4])
{
    #pragma unroll
    for (int j = 0; j < 4; j++) {
        int idx = tid + j * 256;
        int t = idx >> 5, d4 = idx & 31;
        if (gt < 128) {
            size_t base = ((size_t)(b * PAST + gt * 32 + t) * 8 + g) * 128 + d4 * 4;
            kr[j] = *(const float4*)(pk + base);
            vr[j] = *(const float4*)(pv + base);
        } else if (t < 4) {
            size_t base = ((size_t)(b * 4 + t) * 8 + g) * 128 + d4 * 4;
            kr[j] = *(const float4*)(g_knew + base);
            vr[j] = *(const float4*)(g_vnew + base);
        } else {
            kr[j] = make_float4(0.f, 0.f, 0.f, 0.f);
            vr[j] = make_float4(0.f, 0.f, 0.f, 0.f);
        }
    }
}

__global__ __launch_bounds__(256) void attn_kernel(
    const float* __restrict__ past_k, const float* __restrict__ past_v,
    float* __restrict__ out_newk, float* __restrict__ out_newv)
{
    __shared__ float4 qs[16][32];
    __shared__ float4 ksm[32][32];
    __shared__ float4 vsm[32][32];

    const int tid = threadIdx.x;
    const int lane = tid & 31, w = tid >> 5;
    const int bg = blockIdx.x >> 2, sp = blockIdx.x & 3;
    const int b = bg >> 3, g = bg & 7;

    // load roped Q for this (b,g): 16 rows (s,r) x 128
    for (int i = tid; i < 512; i += 256) {
        int q = i >> 5, d4 = i & 31;
        int s = q >> 2, r = q & 3;
        qs[q][d4] = *(const float4*)&g_q[(size_t)(b * 4 + s) * 4096 +
                                         (g * 4 + r) * 128 + d4 * 4];
    }

    const int q0 = 2 * w, q1 = 2 * w + 1;
    float m0 = -1e30f, m1 = -1e30f, l0 = 0.f, l1 = 0.f;
    float4 o0 = make_float4(0.f, 0.f, 0.f, 0.f);
    float4 o1 = make_float4(0.f, 0.f, 0.f, 0.f);
    const float scale = 0.08838834764831845f;   // 1/sqrt(128)

    const int nt = (sp == 3) ? 33 : 32;          // split 3 handles new rows too
    float4 kr[4], vr[4];
    load_tile(sp * 32, tid, b, g, past_k, past_v, kr, vr);

    for (int lt = 0; lt < nt; lt++) {
        const int gt = sp * 32 + lt;             // global tile (128 = new rows)
        if (lt) __syncthreads();                 // smem reuse barrier
        // store tile to smem (XOR swizzle) + fused cache copy-out
        #pragma unroll
        for (int j = 0; j < 4; j++) {
            int idx = tid + j * 256;
            int t = idx >> 5, d4 = idx & 31;
            ksm[t][d4 ^ t] = kr[j];
            vsm[t][d4 ^ t] = vr[j];
            if (gt < 128) {
                size_t ob = ((size_t)(b * TOT + gt * 32 + t) * 8 + g) * 128 + d4 * 4;
                *(float4*)&out_newk[ob] = kr[j];
                *(float4*)&out_newv[ob] = vr[j];
            }
        }
        __syncthreads();
        if (lt + 1 < nt) load_tile(gt + 1, tid, b, g, past_k, past_v, kr, vr);

        // scores: warp w -> q rows {q0,q1}, lane -> t
        float s0 = 0.f, s1 = 0.f;
        #pragma unroll
        for (int d4 = 0; d4 < 32; d4++) {
            float4 kk = ksm[lane][d4 ^ lane];
            float4 qa = qs[q0][d4];
            float4 qb = qs[q1][d4];
            s0 += qa.x * kk.x + qa.y * kk.y + qa.z * kk.z + qa.w * kk.w;
            s1 += qb.x * kk.x + qb.y * kk.y + qb.z * kk.z + qb.w * kk.w;
        }
        s0 *= scale;
        s1 *= scale;
        if (gt == 128 && lane >= 4) { s0 = -1e30f; s1 = -1e30f; }

        // online softmax (warp-local)
        float mt0 = s0, mt1 = s1;
        #pragma unroll
        for (int off = 16; off > 0; off >>= 1) {
            mt0 = fmaxf(mt0, __shfl_xor_sync(FULLMASK, mt0, off));
            mt1 = fmaxf(mt1, __shfl_xor_sync(FULLMASK, mt1, off));
        }
        float mn0 = fmaxf(m0, mt0), mn1 = fmaxf(m1, mt1);
        float a0 = expf(m0 - mn0), a1 = expf(m1 - mn1);
        float p0 = expf(s0 - mn0), p1 = expf(s1 - mn1);
        float sp0 = p0, sp1 = p1;
        #pragma unroll
        for (int off = 16; off > 0; off >>= 1) {
            sp0 += __shfl_xor_sync(FULLMASK, sp0, off);
            sp1 += __shfl_xor_sync(FULLMASK, sp1, off);
        }
        l0 = l0 * a0 + sp0;
        l1 = l1 * a1 + sp1;
        m0 = mn0; m1 = mn1;
        o0.x *= a0; o0.y *= a0; o0.z *= a0; o0.w *= a0;
        o1.x *= a1; o1.y *= a1; o1.z *= a1; o1.w *= a1;

        // PV: lane -> d4, broadcast P via shuffle
        #pragma unroll
        for (int t = 0; t < 32; t++) {
            float pp0 = __shfl_sync(FULLMASK, p0, t);
            float pp1 = __shfl_sync(FULLMASK, p1, t);
            float4 vv = vsm[t][lane ^ t];
            o0.x += pp0 * vv.x; o0.y += pp0 * vv.y;
            o0.z += pp0 * vv.z; o0.w += pp0 * vv.w;
            o1.x += pp1 * vv.x; o1.y += pp1 * vv.y;
            o1.z += pp1 * vv.z; o1.w += pp1 * vv.w;
        }
    }

    // write unnormalized partials for this split
    const int blk = blockIdx.x;
    if (lane == 0) {
        g_pm[blk * 16 + q0] = m0;  g_pl[blk * 16 + q0] = l0;
        g_pm[blk * 16 + q1] = m1;  g_pl[blk * 16 + q1] = l1;
    }
    *(float4*)&g_po[((size_t)blk * 16 + q0) * 128 + lane * 4] = o0;
    *(float4*)&g_po[((size_t)blk * 16 + q1) * 128 + lane * 4] = o1;
}

// --------------------- combine split-KV partials -> g_attn ------------------
__global__ __launch_bounds__(256) void attn_combine()
{
    const int tid = threadIdx.x;
    const int lane = tid & 31, w = tid >> 5;
    const int bg = blockIdx.x;
    const int b = bg >> 3, g = bg & 7;

    #pragma unroll
    for (int qi = 0; qi < 2; qi++) {
        int q = 2 * w + qi;
        float ms[4];
        float M = -1e30f;
        #pragma unroll
        for (int s = 0; s < 4; s++) {
            ms[s] = g_pm[(bg * 4 + s) * 16 + q];
            M = fmaxf(M, ms[s]);
        }
        float L = 0.f;
        float4 acc = make_float4(0.f, 0.f, 0.f, 0.f);
        #pragma unroll
        for (int s = 0; s < 4; s++) {
            float sc = expf(ms[s] - M);
            L += sc * g_pl[(bg * 4 + s) * 16 + q];
            float4 po = *(const float4*)&g_po[((size_t)(bg * 4 + s) * 16 + q) * 128 + lane * 4];
            acc.x += sc * po.x; acc.y += sc * po.y;
            acc.z += sc * po.z; acc.w += sc * po.w;
        }
        float inv = 1.f / L;
        acc.x *= inv; acc.y *= inv; acc.z *= inv; acc.w *= inv;
        int st = q >> 2, r = q & 3;
        *(float4*)&g_attn[(size_t)(b * 4 + st) * 4096 + (g * 4 + r) * 128 + lane * 4] = acc;
    }
}

// --------------------- final split-K reduce for output ----------------------
__global__ __launch_bounds__(256) void reduce_out(float* __restrict__ out)
{
    int idx = blockIdx.x * 256 + threadIdx.x;   // 262144
    int m = idx >> 12, n = idx & 4095;
    float v = 0.f;
    #pragma unroll
    for (int ks = 0; ks < KS; ks++)
        v += g_part[(size_t)(ks * 64 + m) * 4096 + n];
    out[idx] = v;
}

// -----------------------------------------------------------------------------
extern "C" void kernel_launch(void* const* d_in, const int* in_sizes, int n_in,
                              void* d_out, int out_size)
{
    const int*   positions = (const int*)  d_in[0];
    const float* hidden    = (const float*)d_in[1];
    const float* past_k    = (const float*)d_in[2];
    const float* past_v    = (const float*)d_in[3];
    const float* w_qkv     = (const float*)d_in[4];
    const float* w_o       = (const float*)d_in[5];

    float* out      = (float*)d_out;
    float* out_newk = out + OUT_OFF;
    float* out_newv = out_newk + NEWK_ELEMS;

    gemm_splitk<<<dim3(48, KS), 256>>>(hidden, w_qkv, 6144, 0);
    reduce_rope<<<896, 256>>>(positions, out_newk, out_newv);
    attn_kernel<<<512, 256>>>(past_k, past_v, out_newk, out_newv);
    attn_combine<<<128, 256>>>();
    gemm_splitk<<<dim3(32, KS), 256>>>(nullptr, w_o, 4096, 1);
    reduce_out<<<1024, 256>>>(out);
}

// round 6
// speedup vs baseline: 1.1429x; 1.0938x over previous
#include <cuda_runtime.h>
#include <math.h>

#define FULLMASK 0xffffffffu
#define NTOK 64
#define PAST 4096
#define TOT  4100
#define OUT_OFF 262144
#define NEWK_ELEMS 67174400
#define KS 16

typedef unsigned long long ull;

// ---------------------- packed fp32x2 helpers (sm_103a) ---------------------
__device__ __forceinline__ ull pk2(float lo, float hi) {
    ull r;
    asm("mov.b64 %0, {%1, %2};" : "=l"(r) : "f"(lo), "f"(hi));
    return r;
}
__device__ __forceinline__ ull ffma2(ull a, ull b, ull c) {
    ull d;
    asm("fma.rn.f32x2 %0, %1, %2, %3;" : "=l"(d) : "l"(a), "l"(b), "l"(c));
    return d;
}
__device__ __forceinline__ ull fmul2(ull a, ull b) {
    ull d;
    asm("mul.rn.f32x2 %0, %1, %2;" : "=l"(d) : "l"(a), "l"(b));
    return d;
}
__device__ __forceinline__ float2 upk2(ull v) {
    float2 r;
    asm("mov.b64 {%0, %1}, %2;" : "=f"(r.x), "=f"(r.y) : "l"(v));
    return r;
}

// ------------------------- scratch (allocation-free) ------------------------
__device__ float g_part[KS * 64 * 6144];    // split-K partials
__device__ float g_q   [64 * 4096];         // roped Q, token-major
__device__ float g_attn[64 * 4096];         // attention output (pre w_o)
__device__ float g_knew[64 * 8 * 128];      // roped new K rows
__device__ float g_vnew[64 * 8 * 128];      // new V rows
__device__ float g_po  [512 * 16 * 128];    // split-KV partial O (unnormalized)
__device__ float g_pm  [512 * 16];          // split-KV partial max
__device__ float g_pl  [512 * 16];          // split-KV partial sum

// ------------------------------ split-K GEMM --------------------------------
// C_partial[ks][64][N] = A[64, 4096(chunk ks)] @ W[4096, N]
// CTA tile 64x128, 256 thr, 8m x 4n per thread via f32x2 (16 FFMA2/k-step).
__global__ __launch_bounds__(256) void gemm_splitk(
    const float* __restrict__ Ain, const float* __restrict__ W,
    int N, int useAttn)
{
    const float* A = useAttn ? g_attn : Ain;
    __shared__ float As[2][16][64];
    __shared__ float Bs[2][16][128];

    const int tid = threadIdx.x;
    const int n0  = blockIdx.x * 128;
    const int kbase = blockIdx.y * 256;          // Kchunk = 256, KS = 16

    const int lm = tid >> 2,  lk = (tid & 3) << 2;
    const int bk = tid >> 4,  bn = (tid & 15) << 3;

    const float* Ap = A + (size_t)lm * 4096 + kbase + lk;
    const float* Wp = W + (size_t)(kbase + bk) * N + n0 + bn;

    float4 ar  = *(const float4*)Ap;
    float4 br0 = *(const float4*)Wp;
    float4 br1 = *(const float4*)(Wp + 4);

    const int tm = (tid >> 5) << 3;
    const int tn = (tid & 31) << 2;

    ull acc[4][4];                               // [m-pair][n]
    #pragma unroll
    for (int p = 0; p < 4; p++)
        #pragma unroll
        for (int j = 0; j < 4; j++) acc[p][j] = 0ull;

    for (int st = 0; st < 16; st++) {            // 16 stages * 16 = 256
        const int cur = st & 1;
        As[cur][lk + 0][lm] = ar.x;
        As[cur][lk + 1][lm] = ar.y;
        As[cur][lk + 2][lm] = ar.z;
        As[cur][lk + 3][lm] = ar.w;
        *(float4*)&Bs[cur][bk][bn]     = br0;
        *(float4*)&Bs[cur][bk][bn + 4] = br1;
        __syncthreads();
        if (st + 1 < 16) {
            ar  = *(const float4*)(Ap + (st + 1) * 16);
            br0 = *(const float4*)(Wp + (size_t)(st + 1) * 16 * N);
            br1 = *(const float4*)(Wp + (size_t)(st + 1) * 16 * N + 4);
        }
        #pragma unroll
        for (int k = 0; k < 16; k++) {
            float4 b4  = *(const float4*)&Bs[cur][k][tn];
            float4 alo = *(const float4*)&As[cur][k][tm];
            float4 ahi = *(const float4*)&As[cur][k][tm + 4];
            ull am[4];
            am[0] = pk2(alo.x, alo.y);
            am[1] = pk2(alo.z, alo.w);
            am[2] = pk2(ahi.x, ahi.y);
            am[3] = pk2(ahi.z, ahi.w);
            ull bx = pk2(b4.x, b4.x);
            ull by = pk2(b4.y, b4.y);
            ull bz = pk2(b4.z, b4.z);
            ull bw = pk2(b4.w, b4.w);
            #pragma unroll
            for (int p = 0; p < 4; p++) {
                acc[p][0] = ffma2(am[p], bx, acc[p][0]);
                acc[p][1] = ffma2(am[p], by, acc[p][1]);
                acc[p][2] = ffma2(am[p], bz, acc[p][2]);
                acc[p][3] = ffma2(am[p], bw, acc[p][3]);
            }
        }
    }

    float* out = g_part + (size_t)blockIdx.y * 64 * N;
    #pragma unroll
    for (int p = 0; p < 4; p++) {
        float2 c0 = upk2(acc[p][0]);
        float2 c1 = upk2(acc[p][1]);
        float2 c2 = upk2(acc[p][2]);
        float2 c3 = upk2(acc[p][3]);
        *(float4*)&out[(size_t)(tm + 2*p)     * N + n0 + tn] =
            make_float4(c0.x, c1.x, c2.x, c3.x);
        *(float4*)&out[(size_t)(tm + 2*p + 1) * N + n0 + tn] =
            make_float4(c0.y, c1.y, c2.y, c3.y);
    }
}

// ---------------- reduce split-K partials + RoPE + scatter ------------------
__global__ __launch_bounds__(256) void reduce_rope(
    const int* __restrict__ positions,
    float* __restrict__ out_newk, float* __restrict__ out_newv)
{
    int idx = blockIdx.x * 256 + threadIdx.x;    // 229376 total
    if (idx < 131072) {                          // Q rope pairs: 64*32*64
        int tok = idx >> 11;
        int rem = idx & 2047;
        int h = rem >> 6, d = rem & 63;
        int col = h * 128 + d;
        float v1 = 0.f, v2 = 0.f;
        #pragma unroll
        for (int ks = 0; ks < KS; ks++) {
            const float* p = g_part + (size_t)(ks * 64 + tok) * 6144;
            v1 += p[col];
            v2 += p[col + 64];
        }
        float pos = (float)positions[tok];
        float inv = powf(500000.0f, -(float)d * (1.0f / 64.0f));
        float sn, cs;
        sincosf(pos * inv, &sn, &cs);
        g_q[tok * 4096 + col]      = v1 * cs - v2 * sn;
        g_q[tok * 4096 + col + 64] = v2 * cs + v1 * sn;
    } else if (idx < 163840) {                   // K rope pairs: 64*8*64
        int j = idx - 131072;
        int tok = j >> 9;
        int rem = j & 511;
        int kv = rem >> 6, d = rem & 63;
        int col = 4096 + kv * 128 + d;
        float v1 = 0.f, v2 = 0.f;
        #pragma unroll
        for (int ks = 0; ks < KS; ks++) {
            const float* p = g_part + (size_t)(ks * 64 + tok) * 6144;
            v1 += p[col];
            v2 += p[col + 64];
        }
        float pos = (float)positions[tok];
        float inv = powf(500000.0f, -(float)d * (1.0f / 64.0f));
        float sn, cs;
        sincosf(pos * inv, &sn, &cs);
        float o1 = v1 * cs - v2 * sn;
        float o2 = v2 * cs + v1 * sn;
        g_knew[(tok * 8 + kv) * 128 + d]      = o1;
        g_knew[(tok * 8 + kv) * 128 + d + 64] = o2;
        int b = tok >> 2, s = tok & 3;
        size_t oo = ((size_t)(b * TOT + PAST + s) * 8 + kv) * 128 + d;
        out_newk[oo]      = o1;
        out_newk[oo + 64] = o2;
    } else {                                     // V passthrough: 64*8*128
        int j = idx - 163840;
        int tok = j >> 10;
        int rem = j & 1023;
        int kv = rem >> 7, d = rem & 127;
        int col = 5120 + kv * 128 + d;
        float v = 0.f;
        #pragma unroll
        for (int ks = 0; ks < KS; ks++)
            v += g_part[(size_t)(ks * 64 + tok) * 6144 + col];
        g_vnew[(tok * 8 + kv) * 128 + d] = v;
        int b = tok >> 2, s = tok & 3;
        out_newv[((size_t)(b * TOT + PAST + s) * 8 + kv) * 128 + d] = v;
    }
}

// ----------------- fused attention + KV-cache copy (split-KV x4) ------------
__device__ __forceinline__ void load_tile(
    int gt, int tid, int b, int g,
    const float* __restrict__ pk, const float* __restrict__ pv,
    float4 kr[4], float4 vr[4])
{
    #pragma unroll
    for (int j = 0; j < 4; j++) {
        int idx = tid + j * 256;
        int t = idx >> 5, d4 = idx & 31;
        if (gt < 128) {
            size_t base = ((size_t)(b * PAST + gt * 32 + t) * 8 + g) * 128 + d4 * 4;
            kr[j] = *(const float4*)(pk + base);
            vr[j] = *(const float4*)(pv + base);
        } else if (t < 4) {
            size_t base = ((size_t)(b * 4 + t) * 8 + g) * 128 + d4 * 4;
            kr[j] = *(const float4*)(g_knew + base);
            vr[j] = *(const float4*)(g_vnew + base);
        } else {
            kr[j] = make_float4(0.f, 0.f, 0.f, 0.f);
            vr[j] = make_float4(0.f, 0.f, 0.f, 0.f);
        }
    }
}

__global__ __launch_bounds__(256) void attn_kernel(
    const float* __restrict__ past_k, const float* __restrict__ past_v,
    float* __restrict__ out_newk, float* __restrict__ out_newv)
{
    __shared__ float4 qs[16][32];
    __shared__ float4 ksm[32][32];
    __shared__ float4 vsm[32][32];

    const int tid = threadIdx.x;
    const int lane = tid & 31, w = tid >> 5;
    const int bg = blockIdx.x >> 2, sp = blockIdx.x & 3;
    const int b = bg >> 3, g = bg & 7;

    for (int i = tid; i < 512; i += 256) {
        int q = i >> 5, d4 = i & 31;
        int s = q >> 2, r = q & 3;
        qs[q][d4] = *(const float4*)&g_q[(size_t)(b * 4 + s) * 4096 +
                                         (g * 4 + r) * 128 + d4 * 4];
    }

    const int q0 = 2 * w, q1 = 2 * w + 1;
    float m0 = -1e30f, m1 = -1e30f, l0 = 0.f, l1 = 0.f;
    ull o0lo = 0ull, o0hi = 0ull, o1lo = 0ull, o1hi = 0ull;
    const float scale = 0.08838834764831845f;   // 1/sqrt(128)

    const int nt = (sp == 3) ? 33 : 32;
    float4 kr[4], vr[4];
    load_tile(sp * 32, tid, b, g, past_k, past_v, kr, vr);

    for (int lt = 0; lt < nt; lt++) {
        const int gt = sp * 32 + lt;
        if (lt) __syncthreads();
        #pragma unroll
        for (int j = 0; j < 4; j++) {
            int idx = tid + j * 256;
            int t = idx >> 5, d4 = idx & 31;
            ksm[t][d4 ^ t] = kr[j];
            vsm[t][d4 ^ t] = vr[j];
            if (gt < 128) {
                size_t ob = ((size_t)(b * TOT + gt * 32 + t) * 8 + g) * 128 + d4 * 4;
                *(float4*)&out_newk[ob] = kr[j];
                *(float4*)&out_newv[ob] = vr[j];
            }
        }
        __syncthreads();
        if (lt + 1 < nt) load_tile(gt + 1, tid, b, g, past_k, past_v, kr, vr);

        // scores (f32x2, 2 accumulator chains per q-row)
        ull s0a = 0ull, s0b = 0ull, s1a = 0ull, s1b = 0ull;
        #pragma unroll
        for (int d4 = 0; d4 < 32; d4++) {
            float4 kk = ksm[lane][d4 ^ lane];
            float4 qa = qs[q0][d4];
            float4 qb = qs[q1][d4];
            ull k01 = pk2(kk.x, kk.y), k23 = pk2(kk.z, kk.w);
            s0a = ffma2(pk2(qa.x, qa.y), k01, s0a);
            s0b = ffma2(pk2(qa.z, qa.w), k23, s0b);
            s1a = ffma2(pk2(qb.x, qb.y), k01, s1a);
            s1b = ffma2(pk2(qb.z, qb.w), k23, s1b);
        }
        float2 f0a = upk2(s0a), f0b = upk2(s0b);
        float2 f1a = upk2(s1a), f1b = upk2(s1b);
        float s0 = (f0a.x + f0a.y + f0b.x + f0b.y) * scale;
        float s1 = (f1a.x + f1a.y + f1b.x + f1b.y) * scale;
        if (gt == 128 && lane >= 4) { s0 = -1e30f; s1 = -1e30f; }

        // online softmax (warp-local)
        float mt0 = s0, mt1 = s1;
        #pragma unroll
        for (int off = 16; off > 0; off >>= 1) {
            mt0 = fmaxf(mt0, __shfl_xor_sync(FULLMASK, mt0, off));
            mt1 = fmaxf(mt1, __shfl_xor_sync(FULLMASK, mt1, off));
        }
        float mn0 = fmaxf(m0, mt0), mn1 = fmaxf(m1, mt1);
        float a0 = __expf(m0 - mn0), a1 = __expf(m1 - mn1);
        float p0 = __expf(s0 - mn0), p1 = __expf(s1 - mn1);
        float sp0 = p0, sp1 = p1;
        #pragma unroll
        for (int off = 16; off > 0; off >>= 1) {
            sp0 += __shfl_xor_sync(FULLMASK, sp0, off);
            sp1 += __shfl_xor_sync(FULLMASK, sp1, off);
        }
        l0 = l0 * a0 + sp0;
        l1 = l1 * a1 + sp1;
        m0 = mn0; m1 = mn1;
        ull A0 = pk2(a0, a0), A1 = pk2(a1, a1);
        o0lo = fmul2(o0lo, A0); o0hi = fmul2(o0hi, A0);
        o1lo = fmul2(o1lo, A1); o1hi = fmul2(o1hi, A1);

        // PV (f32x2): lane -> d4, broadcast P via shuffle
        #pragma unroll
        for (int t = 0; t < 32; t++) {
            float pp0 = __shfl_sync(FULLMASK, p0, t);
            float pp1 = __shfl_sync(FULLMASK, p1, t);
            float4 vv = vsm[t][lane ^ t];
            ull v01 = pk2(vv.x, vv.y), v23 = pk2(vv.z, vv.w);
            ull P0 = pk2(pp0, pp0), P1 = pk2(pp1, pp1);
            o0lo = ffma2(P0, v01, o0lo);
            o0hi = ffma2(P0, v23, o0hi);
            o1lo = ffma2(P1, v01, o1lo);
            o1hi = ffma2(P1, v23, o1hi);
        }
    }

    // write unnormalized partials for this split
    const int blk = blockIdx.x;
    if (lane == 0) {
        g_pm[blk * 16 + q0] = m0;  g_pl[blk * 16 + q0] = l0;
        g_pm[blk * 16 + q1] = m1;  g_pl[blk * 16 + q1] = l1;
    }
    float2 e0 = upk2(o0lo), e1 = upk2(o0hi);
    *(float4*)&g_po[((size_t)blk * 16 + q0) * 128 + lane * 4] =
        make_float4(e0.x, e0.y, e1.x, e1.y);
    float2 e2 = upk2(o1lo), e3 = upk2(o1hi);
    *(float4*)&g_po[((size_t)blk * 16 + q1) * 128 + lane * 4] =
        make_float4(e2.x, e2.y, e3.x, e3.y);
}

// --------------------- combine split-KV partials -> g_attn ------------------
__global__ __launch_bounds__(256) void attn_combine()
{
    const int tid = threadIdx.x;
    const int lane = tid & 31, w = tid >> 5;
    const int bg = blockIdx.x;
    const int b = bg >> 3, g = bg & 7;

    #pragma unroll
    for (int qi = 0; qi < 2; qi++) {
        int q = 2 * w + qi;
        float ms[4];
        float M = -1e30f;
        #pragma unroll
        for (int s = 0; s < 4; s++) {
            ms[s] = g_pm[(bg * 4 + s) * 16 + q];
            M = fmaxf(M, ms[s]);
        }
        float L = 0.f;
        float4 acc = make_float4(0.f, 0.f, 0.f, 0.f);
        #pragma unroll
        for (int s = 0; s < 4; s++) {
            float sc = __expf(ms[s] - M);
            L += sc * g_pl[(bg * 4 + s) * 16 + q];
            float4 po = *(const float4*)&g_po[((size_t)(bg * 4 + s) * 16 + q) * 128 + lane * 4];
            acc.x += sc * po.x; acc.y += sc * po.y;
            acc.z += sc * po.z; acc.w += sc * po.w;
        }
        float inv = 1.f / L;
        acc.x *= inv; acc.y *= inv; acc.z *= inv; acc.w *= inv;
        int st = q >> 2, r = q & 3;
        *(float4*)&g_attn[(size_t)(b * 4 + st) * 4096 + (g * 4 + r) * 128 + lane * 4] = acc;
    }
}

// --------------------- final split-K reduce for output ----------------------
__global__ __launch_bounds__(256) void reduce_out(float* __restrict__ out)
{
    int idx = blockIdx.x * 256 + threadIdx.x;   // 262144
    int m = idx >> 12, n = idx & 4095;
    float v = 0.f;
    #pragma unroll
    for (int ks = 0; ks < KS; ks++)
        v += g_part[(size_t)(ks * 64 + m) * 4096 + n];
    out[idx] = v;
}

// -----------------------------------------------------------------------------
extern "C" void kernel_launch(void* const* d_in, const int* in_sizes, int n_in,
                              void* d_out, int out_size)
{
    const int*   positions = (const int*)  d_in[0];
    const float* hidden    = (const float*)d_in[1];
    const float* past_k    = (const float*)d_in[2];
    const float* past_v    = (const float*)d_in[3];
    const float* w_qkv     = (const float*)d_in[4];
    const float* w_o       = (const float*)d_in[5];

    float* out      = (float*)d_out;
    float* out_newk = out + OUT_OFF;
    float* out_newv = out_newk + NEWK_ELEMS;

    gemm_splitk<<<dim3(48, KS), 256>>>(hidden, w_qkv, 6144, 0);
    reduce_rope<<<896, 256>>>(positions, out_newk, out_newv);
    attn_kernel<<<512, 256>>>(past_k, past_v, out_newk, out_newv);
    attn_combine<<<128, 256>>>();
    gemm_splitk<<<dim3(32, KS), 256>>>(nullptr, w_o, 4096, 1);
    reduce_out<<<1024, 256>>>(out);
}

// round 7
// speedup vs baseline: 1.2628x; 1.1050x over previous
#include <cuda_runtime.h>
#include <math.h>

#define FULLMASK 0xffffffffu
#define NTOK 64
#define PAST 4096
#define TOT  4100
#define OUT_OFF 262144
#define NEWK_ELEMS 67174400
#define KS 16

typedef unsigned long long ull;

// ---------------------- packed fp32x2 helpers (sm_103a) ---------------------
__device__ __forceinline__ ull pk2(float lo, float hi) {
    ull r;
    asm("mov.b64 %0, {%1, %2};" : "=l"(r) : "f"(lo), "f"(hi));
    return r;
}
__device__ __forceinline__ ull ffma2(ull a, ull b, ull c) {
    ull d;
    asm("fma.rn.f32x2 %0, %1, %2, %3;" : "=l"(d) : "l"(a), "l"(b), "l"(c));
    return d;
}
__device__ __forceinline__ ull fmul2(ull a, ull b) {
    ull d;
    asm("mul.rn.f32x2 %0, %1, %2;" : "=l"(d) : "l"(a), "l"(b));
    return d;
}
__device__ __forceinline__ float2 upk2(ull v) {
    float2 r;
    asm("mov.b64 {%0, %1}, %2;" : "=f"(r.x), "=f"(r.y) : "l"(v));
    return r;
}

// ------------------------- scratch (allocation-free) ------------------------
__device__ float g_part[KS * 64 * 6144];    // split-K partials
__device__ float g_q   [64 * 4096];         // roped Q, token-major
__device__ float g_attn[64 * 4096];         // attention output (pre w_o)
__device__ float g_knew[64 * 8 * 128];      // roped new K rows
__device__ float g_vnew[64 * 8 * 128];      // new V rows
__device__ float g_po  [512 * 32 * 128];    // per-(CTA,warp) partial O rows
__device__ float g_pm  [512 * 32];          // partial max per row-of-8q
__device__ float g_pl  [512 * 32];          // partial sum

// ------------------------------ split-K GEMM --------------------------------
__global__ __launch_bounds__(256) void gemm_splitk(
    const float* __restrict__ Ain, const float* __restrict__ W,
    int N, int useAttn)
{
    const float* A = useAttn ? g_attn : Ain;
    __shared__ float As[2][16][64];
    __shared__ float Bs[2][16][128];

    const int tid = threadIdx.x;
    const int n0  = blockIdx.x * 128;
    const int kbase = blockIdx.y * 256;          // Kchunk = 256, KS = 16

    const int lm = tid >> 2,  lk = (tid & 3) << 2;
    const int bk = tid >> 4,  bn = (tid & 15) << 3;

    const float* Ap = A + (size_t)lm * 4096 + kbase + lk;
    const float* Wp = W + (size_t)(kbase + bk) * N + n0 + bn;

    float4 ar  = *(const float4*)Ap;
    float4 br0 = *(const float4*)Wp;
    float4 br1 = *(const float4*)(Wp + 4);

    const int tm = (tid >> 5) << 3;
    const int tn = (tid & 31) << 2;

    ull acc[4][4];
    #pragma unroll
    for (int p = 0; p < 4; p++)
        #pragma unroll
        for (int j = 0; j < 4; j++) acc[p][j] = 0ull;

    for (int st = 0; st < 16; st++) {
        const int cur = st & 1;
        As[cur][lk + 0][lm] = ar.x;
        As[cur][lk + 1][lm] = ar.y;
        As[cur][lk + 2][lm] = ar.z;
        As[cur][lk + 3][lm] = ar.w;
        *(float4*)&Bs[cur][bk][bn]     = br0;
        *(float4*)&Bs[cur][bk][bn + 4] = br1;
        __syncthreads();
        if (st + 1 < 16) {
            ar  = *(const float4*)(Ap + (st + 1) * 16);
            br0 = *(const float4*)(Wp + (size_t)(st + 1) * 16 * N);
            br1 = *(const float4*)(Wp + (size_t)(st + 1) * 16 * N + 4);
        }
        #pragma unroll
        for (int k = 0; k < 16; k++) {
            float4 b4  = *(const float4*)&Bs[cur][k][tn];
            float4 alo = *(const float4*)&As[cur][k][tm];
            float4 ahi = *(const float4*)&As[cur][k][tm + 4];
            ull am[4];
            am[0] = pk2(alo.x, alo.y);
            am[1] = pk2(alo.z, alo.w);
            am[2] = pk2(ahi.x, ahi.y);
            am[3] = pk2(ahi.z, ahi.w);
            ull bx = pk2(b4.x, b4.x);
            ull by = pk2(b4.y, b4.y);
            ull bz = pk2(b4.z, b4.z);
            ull bw = pk2(b4.w, b4.w);
            #pragma unroll
            for (int p = 0; p < 4; p++) {
                acc[p][0] = ffma2(am[p], bx, acc[p][0]);
                acc[p][1] = ffma2(am[p], by, acc[p][1]);
                acc[p][2] = ffma2(am[p], bz, acc[p][2]);
                acc[p][3] = ffma2(am[p], bw, acc[p][3]);
            }
        }
    }

    float* out = g_part + (size_t)blockIdx.y * 64 * N;
    #pragma unroll
    for (int p = 0; p < 4; p++) {
        float2 c0 = upk2(acc[p][0]);
        float2 c1 = upk2(acc[p][1]);
        float2 c2 = upk2(acc[p][2]);
        float2 c3 = upk2(acc[p][3]);
        *(float4*)&out[(size_t)(tm + 2*p)     * N + n0 + tn] =
            make_float4(c0.x, c1.x, c2.x, c3.x);
        *(float4*)&out[(size_t)(tm + 2*p + 1) * N + n0 + tn] =
            make_float4(c0.y, c1.y, c2.y, c3.y);
    }
}

// ---------------- reduce split-K partials + RoPE + scatter ------------------
__global__ __launch_bounds__(256) void reduce_rope(
    const int* __restrict__ positions,
    float* __restrict__ out_newk, float* __restrict__ out_newv)
{
    int idx = blockIdx.x * 256 + threadIdx.x;    // 229376 total
    if (idx < 131072) {                          // Q rope pairs: 64*32*64
        int tok = idx >> 11;
        int rem = idx & 2047;
        int h = rem >> 6, d = rem & 63;
        int col = h * 128 + d;
        float v1 = 0.f, v2 = 0.f;
        #pragma unroll
        for (int ks = 0; ks < KS; ks++) {
            const float* p = g_part + (size_t)(ks * 64 + tok) * 6144;
            v1 += p[col];
            v2 += p[col + 64];
        }
        float pos = (float)positions[tok];
        float inv = powf(500000.0f, -(float)d * (1.0f / 64.0f));
        float sn, cs;
        sincosf(pos * inv, &sn, &cs);
        g_q[tok * 4096 + col]      = v1 * cs - v2 * sn;
        g_q[tok * 4096 + col + 64] = v2 * cs + v1 * sn;
    } else if (idx < 163840) {                   // K rope pairs: 64*8*64
        int j = idx - 131072;
        int tok = j >> 9;
        int rem = j & 511;
        int kv = rem >> 6, d = rem & 63;
        int col = 4096 + kv * 128 + d;
        float v1 = 0.f, v2 = 0.f;
        #pragma unroll
        for (int ks = 0; ks < KS; ks++) {
            const float* p = g_part + (size_t)(ks * 64 + tok) * 6144;
            v1 += p[col];
            v2 += p[col + 64];
        }
        float pos = (float)positions[tok];
        float inv = powf(500000.0f, -(float)d * (1.0f / 64.0f));
        float sn, cs;
        sincosf(pos * inv, &sn, &cs);
        float o1 = v1 * cs - v2 * sn;
        float o2 = v2 * cs + v1 * sn;
        g_knew[(tok * 8 + kv) * 128 + d]      = o1;
        g_knew[(tok * 8 + kv) * 128 + d + 64] = o2;
        int b = tok >> 2, s = tok & 3;
        size_t oo = ((size_t)(b * TOT + PAST + s) * 8 + kv) * 128 + d;
        out_newk[oo]      = o1;
        out_newk[oo + 64] = o2;
    } else {                                     // V passthrough: 64*8*128
        int j = idx - 163840;
        int tok = j >> 10;
        int rem = j & 1023;
        int kv = rem >> 7, d = rem & 127;
        int col = 5120 + kv * 128 + d;
        float v = 0.f;
        #pragma unroll
        for (int ks = 0; ks < KS; ks++)
            v += g_part[(size_t)(ks * 64 + tok) * 6144 + col];
        g_vnew[(tok * 8 + kv) * 128 + d] = v;
        int b = tok >> 2, s = tok & 3;
        out_newv[((size_t)(b * TOT + PAST + s) * 8 + kv) * 128 + d] = v;
    }
}

// ----------------- fused attention + KV-cache copy --------------------------
// grid = 512 CTAs (bg*4+sp), 128 threads. 16-token tiles, 64 tiles per split.
// Warp w: tgroup = w&1 (tokens tbase..tbase+7), qhalf = w>>1 (8 q rows).
// Per-warp independent online softmax; partials merged by attn_combine.
__device__ __forceinline__ void load_tile16(
    int gt, int tid, int b, int g,
    const float* __restrict__ pk, const float* __restrict__ pv,
    float4 kr[4], float4 vr[4])
{
    #pragma unroll
    for (int j = 0; j < 4; j++) {
        int idx = tid + j * 128;
        int t = idx >> 5, d4 = idx & 31;
        if (gt < 256) {
            size_t base = ((size_t)(b * PAST + gt * 16 + t) * 8 + g) * 128 + d4 * 4;
            kr[j] = *(const float4*)(pk + base);
            vr[j] = *(const float4*)(pv + base);
        } else if (t < 4) {
            size_t base = ((size_t)(b * 4 + t) * 8 + g) * 128 + d4 * 4;
            kr[j] = *(const float4*)(g_knew + base);
            vr[j] = *(const float4*)(g_vnew + base);
        } else {
            kr[j] = make_float4(0.f, 0.f, 0.f, 0.f);
            vr[j] = make_float4(0.f, 0.f, 0.f, 0.f);
        }
    }
}

__global__ __launch_bounds__(128) void attn_kernel(
    const float* __restrict__ past_k, const float* __restrict__ past_v,
    float* __restrict__ out_newk, float* __restrict__ out_newv)
{
    __shared__ float4 qsT[32][16];      // [d4][q] transposed Q
    __shared__ float4 ksm[16][32];      // [t][d4^t]
    __shared__ float4 vsm[16][32];
    __shared__ float2 p_sm[4][8][8];    // [warp][tloc][qloc] (p,p) pairs
    __shared__ float  a_w [4][8];       // [warp][qloc] rescale factors

    const int tid  = threadIdx.x;
    const int lane = tid & 31, w = tid >> 5;
    const int tg = w & 1, qh = w >> 1;
    const int tbase = tg * 8, qbase = qh * 8;
    const int tloc  = lane >> 2;                // 0..7
    const int qloc  = (lane & 3) << 1;          // 0,2,4,6
    const int q0 = qbase + qloc, q1 = q0 + 1;

    const int bg = blockIdx.x >> 2, sp = blockIdx.x & 3;
    const int b = bg >> 3, g = bg & 7;

    // load roped Q (transposed) for this (b,g): 16 rows x 128
    for (int i = tid; i < 512; i += 128) {
        int q = i >> 5, d4 = i & 31;
        int s = q >> 2, r = q & 3;
        qsT[d4][q] = *(const float4*)&g_q[(size_t)(b * 4 + s) * 4096 +
                                          (g * 4 + r) * 128 + d4 * 4];
    }

    float m0 = -1e30f, m1 = -1e30f, l0 = 0.f, l1 = 0.f;
    ull Of[8][2];
    #pragma unroll
    for (int q = 0; q < 8; q++) { Of[q][0] = 0ull; Of[q][1] = 0ull; }

    const float scale = 0.08838834764831845f;   // 1/sqrt(128)
    const int nt = (sp == 3) ? 65 : 64;

    float4 kr[4], vr[4];
    load_tile16(sp * 64, tid, b, g, past_k, past_v, kr, vr);

    for (int lt = 0; lt < nt; lt++) {
        const int gt = sp * 64 + lt;            // 0..255 past, 256 = new rows
        if (lt) __syncthreads();
        #pragma unroll
        for (int j = 0; j < 4; j++) {
            int idx = tid + j * 128;
            int t = idx >> 5, d4 = idx & 31;
            ksm[t][d4 ^ t] = kr[j];
            vsm[t][d4 ^ t] = vr[j];
            if (gt < 256) {
                size_t ob = ((size_t)(b * TOT + gt * 16 + t) * 8 + g) * 128 + d4 * 4;
                *(float4*)&out_newk[ob] = kr[j];
                *(float4*)&out_newv[ob] = vr[j];
            }
        }
        __syncthreads();
        if (lt + 1 < nt) load_tile16(gt + 1, tid, b, g, past_k, past_v, kr, vr);

        // ---- scores: lane -> (token tbase+tloc) x (q0,q1) ----
        const int trow = tbase + tloc;
        ull s0a = 0ull, s0b = 0ull, s1a = 0ull, s1b = 0ull;
        #pragma unroll
        for (int d4 = 0; d4 < 32; d4++) {
            float4 kk = ksm[trow][d4 ^ trow];
            float4 qa = qsT[d4][q0];
            float4 qb = qsT[d4][q1];
            ull k01 = pk2(kk.x, kk.y), k23 = pk2(kk.z, kk.w);
            s0a = ffma2(pk2(qa.x, qa.y), k01, s0a);
            s0b = ffma2(pk2(qa.z, qa.w), k23, s0b);
            s1a = ffma2(pk2(qb.x, qb.y), k01, s1a);
            s1b = ffma2(pk2(qb.z, qb.w), k23, s1b);
        }
        float2 f0a = upk2(s0a), f0b = upk2(s0b);
        float2 f1a = upk2(s1a), f1b = upk2(s1b);
        float s0 = (f0a.x + f0a.y + f0b.x + f0b.y) * scale;
        float s1 = (f1a.x + f1a.y + f1b.x + f1b.y) * scale;
        if (gt == 256 && trow >= 4) { s0 = -1e30f; s1 = -1e30f; }

        // ---- online softmax over this warp's 8 tokens (butterfly over tloc)
        float mt0 = s0, mt1 = s1;
        #pragma unroll
        for (int off = 4; off <= 16; off <<= 1) {
            mt0 = fmaxf(mt0, __shfl_xor_sync(FULLMASK, mt0, off));
            mt1 = fmaxf(mt1, __shfl_xor_sync(FULLMASK, mt1, off));
        }
        float mn0 = fmaxf(m0, mt0), mn1 = fmaxf(m1, mt1);
        float a0 = __expf(m0 - mn0), a1 = __expf(m1 - mn1);
        float p0 = __expf(s0 - mn0), p1 = __expf(s1 - mn1);
        float sp0 = p0, sp1 = p1;
        #pragma unroll
        for (int off = 4; off <= 16; off <<= 1) {
            sp0 += __shfl_xor_sync(FULLMASK, sp0, off);
            sp1 += __shfl_xor_sync(FULLMASK, sp1, off);
        }
        l0 = l0 * a0 + sp0;
        l1 = l1 * a1 + sp1;
        m0 = mn0; m1 = mn1;

        // stage p (duplicated pairs) and rescale factors
        *(float4*)&p_sm[w][tloc][qloc] = make_float4(p0, p0, p1, p1);
        if (tloc == 0) { a_w[w][qloc] = a0; a_w[w][qloc + 1] = a1; }
        __syncwarp();

        // ---- rescale O by a(q) ----
        float4 av0 = *(const float4*)&a_w[w][0];
        float4 av1 = *(const float4*)&a_w[w][4];
        float av[8] = {av0.x, av0.y, av0.z, av0.w, av1.x, av1.y, av1.z, av1.w};
        #pragma unroll
        for (int q = 0; q < 8; q++) {
            ull A = pk2(av[q], av[q]);
            Of[q][0] = fmul2(Of[q][0], A);
            Of[q][1] = fmul2(Of[q][1], A);
        }

        // ---- PV: lane -> d4 fragment, all 8 q of this warp ----
        #pragma unroll
        for (int t = 0; t < 8; t++) {
            int row = tbase + t;
            float4 vv = vsm[row][lane ^ row];
            ull v01 = pk2(vv.x, vv.y), v23 = pk2(vv.z, vv.w);
            #pragma unroll
            for (int qp = 0; qp < 4; qp++) {
                ulonglong2 pp = *(const ulonglong2*)&p_sm[w][t][qp * 2];
                Of[2*qp][0]   = ffma2(pp.x, v01, Of[2*qp][0]);
                Of[2*qp][1]   = ffma2(pp.x, v23, Of[2*qp][1]);
                Of[2*qp+1][0] = ffma2(pp.y, v01, Of[2*qp+1][0]);
                Of[2*qp+1][1] = ffma2(pp.y, v23, Of[2*qp+1][1]);
            }
        }
        __syncwarp();                            // p_sm reuse next tile
    }

    // ---- write per-warp partials ----
    const int rowbase = (blockIdx.x * 4 + w) * 8;
    if (lane < 4) {
        g_pm[rowbase + qloc]     = m0;  g_pl[rowbase + qloc]     = l0;
        g_pm[rowbase + qloc + 1] = m1;  g_pl[rowbase + qloc + 1] = l1;
    }
    #pragma unroll
    for (int q = 0; q < 8; q++) {
        float2 lo = upk2(Of[q][0]), hi = upk2(Of[q][1]);
        *(float4*)&g_po[(size_t)(rowbase + q) * 128 + lane * 4] =
            make_float4(lo.x, lo.y, hi.x, hi.y);
    }
}

// --------------------- combine partials -> g_attn ---------------------------
// 8 partials per (bg, q): 4 splits x 2 token-groups.
__global__ __launch_bounds__(256) void attn_combine()
{
    const int tid = threadIdx.x;
    const int lane = tid & 31, w = tid >> 5;
    const int bg = blockIdx.x;
    const int b = bg >> 3, g = bg & 7;

    #pragma unroll
    for (int qi = 0; qi < 2; qi++) {
        int q = 2 * w + qi;
        int wq = (q >> 3) * 2;                   // warp base for this qhalf
        int rows[8];
        float ms[8];
        float M = -1e30f;
        #pragma unroll
        for (int i = 0; i < 8; i++) {            // i = sp*2 + tg
            int sp = i >> 1, tg = i & 1;
            rows[i] = ((bg * 4 + sp) * 4 + wq + tg) * 8 + (q & 7);
            ms[i] = g_pm[rows[i]];
            M = fmaxf(M, ms[i]);
        }
        float L = 0.f;
        float4 acc = make_float4(0.f, 0.f, 0.f, 0.f);
        #pragma unroll
        for (int i = 0; i < 8; i++) {
            float sc = __expf(ms[i] - M);
            L += sc * g_pl[rows[i]];
            float4 po = *(const float4*)&g_po[(size_t)rows[i] * 128 + lane * 4];
            acc.x += sc * po.x; acc.y += sc * po.y;
            acc.z += sc * po.z; acc.w += sc * po.w;
        }
        float inv = 1.f / L;
        acc.x *= inv; acc.y *= inv; acc.z *= inv; acc.w *= inv;
        int st = q >> 2, r = q & 3;
        *(float4*)&g_attn[(size_t)(b * 4 + st) * 4096 + (g * 4 + r) * 128 + lane * 4] = acc;
    }
}

// --------------------- final split-K reduce for output ----------------------
__global__ __launch_bounds__(256) void reduce_out(float* __restrict__ out)
{
    int idx = blockIdx.x * 256 + threadIdx.x;   // 262144
    int m = idx >> 12, n = idx & 4095;
    float v = 0.f;
    #pragma unroll
    for (int ks = 0; ks < KS; ks++)
        v += g_part[(size_t)(ks * 64 + m) * 4096 + n];
    out[idx] = v;
}

// -----------------------------------------------------------------------------
extern "C" void kernel_launch(void* const* d_in, const int* in_sizes, int n_in,
                              void* d_out, int out_size)
{
    const int*   positions = (const int*)  d_in[0];
    const float* hidden    = (const float*)d_in[1];
    const float* past_k    = (const float*)d_in[2];
    const float* past_v    = (const float*)d_in[3];
    const float* w_qkv     = (const float*)d_in[4];
    const float* w_o       = (const float*)d_in[5];

    float* out      = (float*)d_out;
    float* out_newk = out + OUT_OFF;
    float* out_newv = out_newk + NEWK_ELEMS;

    gemm_splitk<<<dim3(48, KS), 256>>>(hidden, w_qkv, 6144, 0);
    reduce_rope<<<896, 256>>>(positions, out_newk, out_newv);
    attn_kernel<<<512, 128>>>(past_k, past_v, out_newk, out_newv);
    attn_combine<<<128, 256>>>();
    gemm_splitk<<<dim3(32, KS), 256>>>(nullptr, w_o, 4096, 1);
    reduce_out<<<1024, 256>>>(out);
}